// round 3
// baseline (speedup 1.0000x reference)
#include <cuda_runtime.h>

// out = cumprod_j( cos(w_j) * cos(x @ W_pre^T + b_pre) ) @ W_post^T + b_post
//
// Analytic reduction of the quantum layer:
//   z_j   = cos(q_weights_j) * cos(angle_j)
//   <Z_i> = prod_{j<=i} z_j            (CNOT chain = prefix-XOR)
//
// Two kernels through a __device__ zq scratch:
//   K1: per-row angles + prefix product  (256 blocks x 512 thr)
//   K2: out = zq @ W_post^T + b_post     (1024 blocks x 256 thr, 1 out/thread)

#define NQ   16
#define DIN  1024
#define DOUT 1024
#define B    256

__device__ float g_zq[B * NQ];   // scratch: cumulative <Z> per row

// ---------------------------------------------------------------- K1
__global__ __launch_bounds__(512, 2)
void k_pre(const float* __restrict__ x,
           const float* __restrict__ W_pre,
           const float* __restrict__ b_pre,
           const float* __restrict__ q_weights)
{
    __shared__ float4 sx[DIN / 4];     // 4 KB: one x row, staged once
    __shared__ float  s_angle[NQ];

    const int row  = blockIdx.x;
    const int tid  = threadIdx.x;
    const int warp = tid >> 5;         // 16 warps = 16 qubits
    const int lane = tid & 31;

    // Issue W_pre loads first (registers) so their latency overlaps x staging.
    const float4* __restrict__ w4 = reinterpret_cast<const float4*>(W_pre + warp * DIN);
    float4 wv[8];
#pragma unroll
    for (int i = 0; i < 8; i++)
        wv[i] = w4[lane + 32 * i];

    // Stage x row into shared memory exactly once.
    const float4* __restrict__ x4 = reinterpret_cast<const float4*>(x + row * DIN);
    if (tid < DIN / 4)
        sx[tid] = x4[tid];
    __syncthreads();

    // Dot product: smem x vs register W_pre.
    float acc = 0.f;
#pragma unroll
    for (int i = 0; i < 8; i++) {
        float4 xv = sx[lane + 32 * i];
        acc += xv.x * wv[i].x + xv.y * wv[i].y + xv.z * wv[i].z + xv.w * wv[i].w;
    }
#pragma unroll
    for (int off = 16; off >= 1; off >>= 1)
        acc += __shfl_xor_sync(0xffffffffu, acc, off);

    if (lane == 0)
        s_angle[warp] = acc + b_pre[warp];
    __syncthreads();

    // Warp 0: z_j = cos(w_j)*cos(angle_j); inclusive prefix product; store row.
    if (warp == 0) {
        float v = 1.f;
        if (lane < NQ)
            v = __cosf(q_weights[lane]) * __cosf(s_angle[lane]);
#pragma unroll
        for (int off = 1; off <= 8; off <<= 1) {
            float t = __shfl_up_sync(0xffffffffu, v, off);
            if (lane >= off) v *= t;
        }
        if (lane < NQ)
            g_zq[row * NQ + lane] = v;
    }
}

// ---------------------------------------------------------------- K2
__global__ __launch_bounds__(256)
void k_post(const float* __restrict__ W_post,
            const float* __restrict__ b_post,
            float* __restrict__ out)
{
    __shared__ float s_zq[NQ];

    const int tid = threadIdx.x;
    const int idx = blockIdx.x * 256 + tid;   // global output index
    const int row = idx >> 10;                // block lies within one row
    const int col = idx & (DOUT - 1);

    if (tid < NQ)
        s_zq[tid] = g_zq[row * NQ + tid];
    __syncthreads();

    const float4* __restrict__ Wp4 = reinterpret_cast<const float4*>(W_post);
    float4 w0 = Wp4[col * 4 + 0];
    float4 w1 = Wp4[col * 4 + 1];
    float4 w2 = Wp4[col * 4 + 2];
    float4 w3 = Wp4[col * 4 + 3];

    float d =  s_zq[0]  * w0.x + s_zq[1]  * w0.y + s_zq[2]  * w0.z + s_zq[3]  * w0.w
             + s_zq[4]  * w1.x + s_zq[5]  * w1.y + s_zq[6]  * w1.z + s_zq[7]  * w1.w
             + s_zq[8]  * w2.x + s_zq[9]  * w2.y + s_zq[10] * w2.z + s_zq[11] * w2.w
             + s_zq[12] * w3.x + s_zq[13] * w3.y + s_zq[14] * w3.z + s_zq[15] * w3.w;

    out[idx] = b_post[col] + d;
}

extern "C" void kernel_launch(void* const* d_in, const int* in_sizes, int n_in,
                              void* d_out, int out_size)
{
    const float* x         = (const float*)d_in[0];   // [256, 1024]
    const float* W_pre     = (const float*)d_in[1];   // [16, 1024]
    const float* b_pre     = (const float*)d_in[2];   // [16]
    const float* q_weights = (const float*)d_in[3];   // [16]
    const float* W_post    = (const float*)d_in[4];   // [1024, 16]
    const float* b_post    = (const float*)d_in[5];   // [1024]
    float* out             = (float*)d_out;           // [256, 1024]

    k_pre <<<B, 512>>>(x, W_pre, b_pre, q_weights);
    k_post<<<(B * DOUT) / 256, 256>>>(W_post, b_post, out);
}